// round 12
// baseline (speedup 1.0000x reference)
#include <cuda_runtime.h>
#include <math.h>

// Problem shape (fixed by the dataset)
#define BB 64
#define SS 4096
#define DXE 512
#define QQ 128
#define DQE 512

#define NSPLIT 16
#define ROWS_PER_SPLIT (SS / NSPLIT)   // 256
#define TPB 256
#define WARPS (TPB / 32)               // 8
#define ROWS_PER_WARP (ROWS_PER_SPLIT / WARPS) // 32

#define KSPLIT 8
#define KCHUNK (DQE / KSPLIT)          // 64

#define QSPLIT 16
#define QC (QQ / QSPLIT)               // 8

#define BGRP 2                         // batches per first_kernel CTA

// Scratch (allocation-free: __device__ globals)
__device__ float g_newq_part[QSPLIT][BB * DQE];
__device__ float g_first_part[KSPLIT][BB * DXE];
__device__ float g_pM[BB * NSPLIT];
__device__ float g_pL[BB * NSPLIT];
__device__ float g_pC[BB * NSPLIT * DXE];
__device__ unsigned int g_cnt[BB];     // zero-init; reset by last CTA each pass

// ---------------------------------------------------------------------------
// Kernel A1: new_q partials, maximal parallelism. (measured ~6.5us)
// ---------------------------------------------------------------------------
__global__ __launch_bounds__(256) void newq_kernel(
    const float* __restrict__ qm,   // [B, Q, DQ]
    const float* __restrict__ p)    // [Q, 1]
{
    const int idx = blockIdx.x * 256 + threadIdx.x; // 0..131071
    const int c   = idx >> 13;                      // Q-chunk 0..15
    const int rem = idx & 8191;
    const int b   = rem >> 7;                       // batch 0..63
    const int d4  = rem & 127;                      // float4 index 0..127

    const float4* qb = reinterpret_cast<const float4*>(
        qm + (size_t)b * QQ * DQE + (size_t)(c * QC) * DQE) + d4;
    const float* pc = p + c * QC;

    const float4 v0 = qb[0 * (DQE / 4)];
    const float4 v1 = qb[1 * (DQE / 4)];
    const float4 v2 = qb[2 * (DQE / 4)];
    const float4 v3 = qb[3 * (DQE / 4)];
    const float4 v4 = qb[4 * (DQE / 4)];
    const float4 v5 = qb[5 * (DQE / 4)];
    const float4 v6 = qb[6 * (DQE / 4)];
    const float4 v7 = qb[7 * (DQE / 4)];
    const float s0 = __ldg(&pc[0]);
    const float s1 = __ldg(&pc[1]);
    const float s2 = __ldg(&pc[2]);
    const float s3 = __ldg(&pc[3]);
    const float s4 = __ldg(&pc[4]);
    const float s5 = __ldg(&pc[5]);
    const float s6 = __ldg(&pc[6]);
    const float s7 = __ldg(&pc[7]);

    float4 r;
    r.x = fmaf(v0.x, s0, v1.x * s1); r.x = fmaf(v2.x, s2, r.x); r.x = fmaf(v3.x, s3, r.x);
    r.x = fmaf(v4.x, s4, r.x); r.x = fmaf(v5.x, s5, r.x); r.x = fmaf(v6.x, s6, r.x); r.x = fmaf(v7.x, s7, r.x);
    r.y = fmaf(v0.y, s0, v1.y * s1); r.y = fmaf(v2.y, s2, r.y); r.y = fmaf(v3.y, s3, r.y);
    r.y = fmaf(v4.y, s4, r.y); r.y = fmaf(v5.y, s5, r.y); r.y = fmaf(v6.y, s6, r.y); r.y = fmaf(v7.y, s7, r.y);
    r.z = fmaf(v0.z, s0, v1.z * s1); r.z = fmaf(v2.z, s2, r.z); r.z = fmaf(v3.z, s3, r.z);
    r.z = fmaf(v4.z, s4, r.z); r.z = fmaf(v5.z, s5, r.z); r.z = fmaf(v6.z, s6, r.z); r.z = fmaf(v7.z, s7, r.z);
    r.w = fmaf(v0.w, s0, v1.w * s1); r.w = fmaf(v2.w, s2, r.w); r.w = fmaf(v3.w, s3, r.w);
    r.w = fmaf(v4.w, s4, r.w); r.w = fmaf(v5.w, s5, r.w); r.w = fmaf(v6.w, s6, r.w); r.w = fmaf(v7.w, s7, r.w);

    reinterpret_cast<float4*>(&g_newq_part[c][b * DQE])[d4] = r;
}

// ---------------------------------------------------------------------------
// Kernel A2 (v3): first_part[kc][b,t] = sum_{d in chunk kc} new_q[b,d]*W[d,t]
// grid = (8, 32) = 256 CTAs x 512 thr.
// ---------------------------------------------------------------------------
__global__ __launch_bounds__(512) void first_kernel(
    const float* __restrict__ W)    // [DQ, DX]
{
    const int kc = blockIdx.x;      // 0..7
    const int bg = blockIdx.y;      // 0..31
    const int t  = threadIdx.x;     // 0..511

    __shared__ float sq[BGRP][KCHUNK];

    if (t < BGRP * KCHUNK) {
        const int j = t >> 6;           // batch within group
        const int d = t & 63;
        const int off = (bg * BGRP + j) * DQE + kc * KCHUNK + d;
        float acc[QSPLIT];
#pragma unroll
        for (int c = 0; c < QSPLIT; c++) acc[c] = g_newq_part[c][off];
        float s = 0.f;
#pragma unroll
        for (int c = 0; c < QSPLIT; c++) s += acc[c];
        sq[j][d] = s;
    }
    __syncthreads();

    float acc0 = 0.f, acc1 = 0.f;
    const float* Wc = W + (size_t)(kc * KCHUNK) * DXE + t;
#pragma unroll 16
    for (int d = 0; d < KCHUNK; d++) {
        const float w = Wc[d * DXE];
        acc0 = fmaf(sq[0][d], w, acc0);
        acc1 = fmaf(sq[1][d], w, acc1);
    }
    g_first_part[kc][(bg * BGRP + 0) * DXE + t] = acc0;
    g_first_part[kc][(bg * BGRP + 1) * DXE + t] = acc1;
}

// ---------------------------------------------------------------------------
// Kernel B: fused scores -> online softmax -> weighted sum over a split of S,
// with fused last-CTA final reduce. grid = (NSPLIT, B), block = 256.
// __launch_bounds__(256, 4): cap regs at 64 -> 4 CTAs/SM so neighbor CTAs'
// loads cover prologue/epilogue memory bubbles. Spills (if any) land in the
// cold reduce tail.
// ---------------------------------------------------------------------------
__global__ __launch_bounds__(TPB, 4) void attn_partial_kernel(
    const float* __restrict__ x,   // [B, S, DX]
    float* __restrict__ out)       // [B, DX]
{
    const int split = blockIdx.x;
    const int b     = blockIdx.y;
    const int t     = threadIdx.x;
    const int w     = t >> 5;
    const int lane  = t & 31;

    __shared__ float sfirst[DXE];
    __shared__ float sm_m[WARPS];
    __shared__ float sm_l[WARPS];
    __shared__ float4 sm_acc[WARPS][DXE / 4];
    __shared__ int s_last;

    // sum the 8 split-K partials of `first` (values dead after smem store)
#pragma unroll
    for (int half = 0; half < 2; half++) {
        const int d = t + half * 256;
        float f = 0.f;
#pragma unroll
        for (int kc = 0; kc < KSPLIT; kc++)
            f += g_first_part[kc][b * DXE + d];
        sfirst[d] = f;
    }
    __syncthreads();

    // Per-lane slice of first (as float4, strided by 32 lanes)
    const float4* sf4 = reinterpret_cast<const float4*>(sfirst);
    const float4 f0 = sf4[lane];
    const float4 f1 = sf4[lane + 32];
    const float4 f2 = sf4[lane + 64];
    const float4 f3 = sf4[lane + 96];

    float m = -INFINITY;
    float l = 0.f;
    float4 a0 = make_float4(0.f, 0.f, 0.f, 0.f);
    float4 a1 = a0, a2 = a0, a3 = a0;

    const float4* xb = reinterpret_cast<const float4*>(
        x + (size_t)b * SS * DXE);
    const int s0 = split * ROWS_PER_SPLIT + w;

    for (int r = 0; r < ROWS_PER_WARP; r++) {
        const int s = s0 + WARPS * r;
        const float4* xr = xb + (size_t)s * (DXE / 4);
        // 4 independent LDG.128 per lane -> MLP = 4
        const float4 v0 = xr[lane];
        const float4 v1 = xr[lane + 32];
        const float4 v2 = xr[lane + 64];
        const float4 v3 = xr[lane + 96];

        // dot(first, x_row)
        float d;
        d = v0.x * f0.x;
        d = fmaf(v0.y, f0.y, d); d = fmaf(v0.z, f0.z, d); d = fmaf(v0.w, f0.w, d);
        d = fmaf(v1.x, f1.x, d); d = fmaf(v1.y, f1.y, d); d = fmaf(v1.z, f1.z, d); d = fmaf(v1.w, f1.w, d);
        d = fmaf(v2.x, f2.x, d); d = fmaf(v2.y, f2.y, d); d = fmaf(v2.z, f2.z, d); d = fmaf(v2.w, f2.w, d);
        d = fmaf(v3.x, f3.x, d); d = fmaf(v3.y, f3.y, d); d = fmaf(v3.z, f3.z, d); d = fmaf(v3.w, f3.w, d);
#pragma unroll
        for (int o = 16; o > 0; o >>= 1)
            d += __shfl_xor_sync(0xffffffffu, d, o);

        // online softmax update (d is warp-uniform -> no divergence)
        if (d > m) {
            const float sc = __expf(m - d);  // exp(-inf)=0 handled on first row
            l *= sc;
            a0.x *= sc; a0.y *= sc; a0.z *= sc; a0.w *= sc;
            a1.x *= sc; a1.y *= sc; a1.z *= sc; a1.w *= sc;
            a2.x *= sc; a2.y *= sc; a2.z *= sc; a2.w *= sc;
            a3.x *= sc; a3.y *= sc; a3.z *= sc; a3.w *= sc;
            m = d;
        }
        const float wgt = __expf(d - m);
        l += wgt;
        a0.x = fmaf(wgt, v0.x, a0.x); a0.y = fmaf(wgt, v0.y, a0.y);
        a0.z = fmaf(wgt, v0.z, a0.z); a0.w = fmaf(wgt, v0.w, a0.w);
        a1.x = fmaf(wgt, v1.x, a1.x); a1.y = fmaf(wgt, v1.y, a1.y);
        a1.z = fmaf(wgt, v1.z, a1.z); a1.w = fmaf(wgt, v1.w, a1.w);
        a2.x = fmaf(wgt, v2.x, a2.x); a2.y = fmaf(wgt, v2.y, a2.y);
        a2.z = fmaf(wgt, v2.z, a2.z); a2.w = fmaf(wgt, v2.w, a2.w);
        a3.x = fmaf(wgt, v3.x, a3.x); a3.y = fmaf(wgt, v3.y, a3.y);
        a3.z = fmaf(wgt, v3.z, a3.z); a3.w = fmaf(wgt, v3.w, a3.w);
    }

    // Stash per-warp partials in shared
    if (lane == 0) { sm_m[w] = m; sm_l[w] = l; }
    sm_acc[w][lane]      = a0;
    sm_acc[w][lane + 32] = a1;
    sm_acc[w][lane + 64] = a2;
    sm_acc[w][lane + 96] = a3;
    __syncthreads();

    // Block combine: 8 warps -> one partial (M, L, ctx[512])
    float M = sm_m[0];
#pragma unroll
    for (int i = 1; i < WARPS; i++) M = fmaxf(M, sm_m[i]);

    float ef[WARPS];
    float L = 0.f;
#pragma unroll
    for (int i = 0; i < WARPS; i++) {
        ef[i] = __expf(sm_m[i] - M);
        L = fmaf(ef[i], sm_l[i], L);
    }

    const float* accf = reinterpret_cast<const float*>(sm_acc); // [WARPS][512]
    const int pidx = b * NSPLIT + split;
    float* pc = g_pC + (size_t)pidx * DXE;
#pragma unroll
    for (int half = 0; half < 2; half++) {
        const int d = t + half * 256;
        float c = 0.f;
#pragma unroll
        for (int i = 0; i < WARPS; i++)
            c = fmaf(ef[i], accf[i * DXE + d], c);
        pc[d] = c;
    }
    if (t == 0) { g_pM[pidx] = M; g_pL[pidx] = L; }

    // ---- fused final reduce: last CTA per batch combines all partials ----
    __syncthreads();             // all partial STGs issued block-wide
    if (t == 0) {
        __threadfence();         // release this CTA's partial
        const unsigned int prev = atomicAdd(&g_cnt[b], 1u);
        s_last = (prev == NSPLIT - 1) ? 1 : 0;
    }
    __syncthreads();
    if (!s_last) return;

    __threadfence();             // acquire: all other CTAs' partials visible

    __shared__ float rM[NSPLIT];
    __shared__ float rL[NSPLIT];
    if (t < NSPLIT) {
        rM[t] = g_pM[b * NSPLIT + t];
        rL[t] = g_pL[b * NSPLIT + t];
    }

    // issue 16 independent per-dim partial loads (L2-hot)
    float cv0[NSPLIT], cv1[NSPLIT];
#pragma unroll
    for (int i = 0; i < NSPLIT; i++) {
        const float* pci = g_pC + (size_t)(b * NSPLIT + i) * DXE;
        cv0[i] = pci[t];
        cv1[i] = pci[t + 256];
    }
    __syncthreads();

    float GM = rM[0];
#pragma unroll
    for (int i = 1; i < NSPLIT; i++) GM = fmaxf(GM, rM[i]);

    float GL = 0.f, c0 = 0.f, c1 = 0.f;
#pragma unroll
    for (int i = 0; i < NSPLIT; i++) {
        const float e = __expf(rM[i] - GM);
        GL = fmaf(e, rL[i], GL);
        c0 = fmaf(e, cv0[i], c0);
        c1 = fmaf(e, cv1[i], c1);
    }
    const float inv = 1.f / GL;
    out[b * DXE + t]       = c0 * inv;
    out[b * DXE + t + 256] = c1 * inv;

    if (t == 0) g_cnt[b] = 0;    // reset for next graph replay
}

// ---------------------------------------------------------------------------
extern "C" void kernel_launch(void* const* d_in, const int* in_sizes, int n_in,
                              void* d_out, int out_size)
{
    const float* x  = (const float*)d_in[0];  // [64, 4096, 512]
    const float* qm = (const float*)d_in[1];  // [64, 128, 512]
    const float* W  = (const float*)d_in[2];  // [512, 512]
    const float* p  = (const float*)d_in[3];  // [128, 1]
    float* out = (float*)d_out;               // [64, 512]

    newq_kernel<<<(QSPLIT * BB * (DQE / 4)) / 256, 256>>>(qm, p);
    first_kernel<<<dim3(KSPLIT, BB / BGRP), 512>>>(W);
    attn_partial_kernel<<<dim3(NSPLIT, BB), TPB>>>(x, out);
}

// round 13
// speedup vs baseline: 1.0208x; 1.0208x over previous
#include <cuda_runtime.h>
#include <math.h>

// Problem shape (fixed by the dataset)
#define BB 64
#define SS 4096
#define DXE 512
#define QQ 128
#define DQE 512

#define NSPLIT 16
#define ROWS_PER_SPLIT (SS / NSPLIT)   // 256
#define TPB 256
#define WARPS (TPB / 32)               // 8
#define ROWS_PER_WARP (ROWS_PER_SPLIT / WARPS) // 32

#define KSPLIT 8
#define KCHUNK (DQE / KSPLIT)          // 64

#define QSPLIT 16
#define QC (QQ / QSPLIT)               // 8

#define BGRP 2                         // batches per first_kernel CTA

// Scratch (allocation-free: __device__ globals)
__device__ float g_newq_part[QSPLIT][BB * DQE];
__device__ float g_first_part[KSPLIT][BB * DXE];
__device__ float g_pM[BB * NSPLIT];
__device__ float g_pL[BB * NSPLIT];
__device__ float g_pC[BB * NSPLIT * DXE];
__device__ unsigned int g_cnt[BB];     // zero-init; reset by last CTA each pass

// ---------------------------------------------------------------------------
// Kernel A1: new_q partials, maximal parallelism. (measured ~6.5us)
// Triggers programmatic completion after its stores so the PDL-launched
// first_kernel can overlap its prologue.
// ---------------------------------------------------------------------------
__global__ __launch_bounds__(256) void newq_kernel(
    const float* __restrict__ qm,   // [B, Q, DQ]
    const float* __restrict__ p)    // [Q, 1]
{
    const int idx = blockIdx.x * 256 + threadIdx.x; // 0..131071
    const int c   = idx >> 13;                      // Q-chunk 0..15
    const int rem = idx & 8191;
    const int b   = rem >> 7;                       // batch 0..63
    const int d4  = rem & 127;                      // float4 index 0..127

    const float4* qb = reinterpret_cast<const float4*>(
        qm + (size_t)b * QQ * DQE + (size_t)(c * QC) * DQE) + d4;
    const float* pc = p + c * QC;

    const float4 v0 = qb[0 * (DQE / 4)];
    const float4 v1 = qb[1 * (DQE / 4)];
    const float4 v2 = qb[2 * (DQE / 4)];
    const float4 v3 = qb[3 * (DQE / 4)];
    const float4 v4 = qb[4 * (DQE / 4)];
    const float4 v5 = qb[5 * (DQE / 4)];
    const float4 v6 = qb[6 * (DQE / 4)];
    const float4 v7 = qb[7 * (DQE / 4)];
    const float s0 = __ldg(&pc[0]);
    const float s1 = __ldg(&pc[1]);
    const float s2 = __ldg(&pc[2]);
    const float s3 = __ldg(&pc[3]);
    const float s4 = __ldg(&pc[4]);
    const float s5 = __ldg(&pc[5]);
    const float s6 = __ldg(&pc[6]);
    const float s7 = __ldg(&pc[7]);

    float4 r;
    r.x = fmaf(v0.x, s0, v1.x * s1); r.x = fmaf(v2.x, s2, r.x); r.x = fmaf(v3.x, s3, r.x);
    r.x = fmaf(v4.x, s4, r.x); r.x = fmaf(v5.x, s5, r.x); r.x = fmaf(v6.x, s6, r.x); r.x = fmaf(v7.x, s7, r.x);
    r.y = fmaf(v0.y, s0, v1.y * s1); r.y = fmaf(v2.y, s2, r.y); r.y = fmaf(v3.y, s3, r.y);
    r.y = fmaf(v4.y, s4, r.y); r.y = fmaf(v5.y, s5, r.y); r.y = fmaf(v6.y, s6, r.y); r.y = fmaf(v7.y, s7, r.y);
    r.z = fmaf(v0.z, s0, v1.z * s1); r.z = fmaf(v2.z, s2, r.z); r.z = fmaf(v3.z, s3, r.z);
    r.z = fmaf(v4.z, s4, r.z); r.z = fmaf(v5.z, s5, r.z); r.z = fmaf(v6.z, s6, r.z); r.z = fmaf(v7.z, s7, r.z);
    r.w = fmaf(v0.w, s0, v1.w * s1); r.w = fmaf(v2.w, s2, r.w); r.w = fmaf(v3.w, s3, r.w);
    r.w = fmaf(v4.w, s4, r.w); r.w = fmaf(v5.w, s5, r.w); r.w = fmaf(v6.w, s6, r.w); r.w = fmaf(v7.w, s7, r.w);

    reinterpret_cast<float4*>(&g_newq_part[c][b * DQE])[d4] = r;

    cudaTriggerProgrammaticLaunchCompletion();
}

// ---------------------------------------------------------------------------
// Kernel A2 (v3): first_part[kc][b,t] = sum_{d in chunk kc} new_q[b,d]*W[d,t]
// grid = (8, 32) = 256 CTAs x 512 thr. PDL consumer of newq, producer for
// attn_partial.
// ---------------------------------------------------------------------------
__global__ __launch_bounds__(512) void first_kernel(
    const float* __restrict__ W)    // [DQ, DX]
{
    const int kc = blockIdx.x;      // 0..7
    const int bg = blockIdx.y;      // 0..31
    const int t  = threadIdx.x;     // 0..511

    __shared__ float sq[BGRP][KCHUNK];

    // wait for newq_kernel's grid (PDL): required before reading g_newq_part
    cudaGridDependencySynchronize();

    if (t < BGRP * KCHUNK) {
        const int j = t >> 6;           // batch within group
        const int d = t & 63;
        const int off = (bg * BGRP + j) * DQE + kc * KCHUNK + d;
        float acc[QSPLIT];
#pragma unroll
        for (int c = 0; c < QSPLIT; c++) acc[c] = g_newq_part[c][off];
        float s = 0.f;
#pragma unroll
        for (int c = 0; c < QSPLIT; c++) s += acc[c];
        sq[j][d] = s;
    }
    __syncthreads();

    float acc0 = 0.f, acc1 = 0.f;
    const float* Wc = W + (size_t)(kc * KCHUNK) * DXE + t;
#pragma unroll 16
    for (int d = 0; d < KCHUNK; d++) {
        const float w = Wc[d * DXE];
        acc0 = fmaf(sq[0][d], w, acc0);
        acc1 = fmaf(sq[1][d], w, acc1);
    }
    g_first_part[kc][(bg * BGRP + 0) * DXE + t] = acc0;
    g_first_part[kc][(bg * BGRP + 1) * DXE + t] = acc1;

    cudaTriggerProgrammaticLaunchCompletion();
}

// ---------------------------------------------------------------------------
// Kernel B: fused scores -> online softmax -> weighted sum over a split of S,
// with fused last-CTA final reduce. grid = (NSPLIT, B), block = 256.
// PDL consumer of first_kernel: grid ramps up / does index math while
// first_kernel drains, then syncs right before reading g_first_part.
// ---------------------------------------------------------------------------
__global__ __launch_bounds__(TPB, 4) void attn_partial_kernel(
    const float* __restrict__ x,   // [B, S, DX]
    float* __restrict__ out)       // [B, DX]
{
    const int split = blockIdx.x;
    const int b     = blockIdx.y;
    const int t     = threadIdx.x;
    const int w     = t >> 5;
    const int lane  = t & 31;

    __shared__ float sfirst[DXE];
    __shared__ float sm_m[WARPS];
    __shared__ float sm_l[WARPS];
    __shared__ float4 sm_acc[WARPS][DXE / 4];
    __shared__ int s_last;

    // wait for first_kernel's grid (PDL)
    cudaGridDependencySynchronize();

    // sum the 8 split-K partials of `first` (values dead after smem store)
#pragma unroll
    for (int half = 0; half < 2; half++) {
        const int d = t + half * 256;
        float f = 0.f;
#pragma unroll
        for (int kc = 0; kc < KSPLIT; kc++)
            f += g_first_part[kc][b * DXE + d];
        sfirst[d] = f;
    }
    __syncthreads();

    // Per-lane slice of first (as float4, strided by 32 lanes)
    const float4* sf4 = reinterpret_cast<const float4*>(sfirst);
    const float4 f0 = sf4[lane];
    const float4 f1 = sf4[lane + 32];
    const float4 f2 = sf4[lane + 64];
    const float4 f3 = sf4[lane + 96];

    float m = -INFINITY;
    float l = 0.f;
    float4 a0 = make_float4(0.f, 0.f, 0.f, 0.f);
    float4 a1 = a0, a2 = a0, a3 = a0;

    const float4* xb = reinterpret_cast<const float4*>(
        x + (size_t)b * SS * DXE);
    const int s0 = split * ROWS_PER_SPLIT + w;

    for (int r = 0; r < ROWS_PER_WARP; r++) {
        const int s = s0 + WARPS * r;
        const float4* xr = xb + (size_t)s * (DXE / 4);
        // 4 independent LDG.128 per lane -> MLP = 4
        const float4 v0 = xr[lane];
        const float4 v1 = xr[lane + 32];
        const float4 v2 = xr[lane + 64];
        const float4 v3 = xr[lane + 96];

        // dot(first, x_row)
        float d;
        d = v0.x * f0.x;
        d = fmaf(v0.y, f0.y, d); d = fmaf(v0.z, f0.z, d); d = fmaf(v0.w, f0.w, d);
        d = fmaf(v1.x, f1.x, d); d = fmaf(v1.y, f1.y, d); d = fmaf(v1.z, f1.z, d); d = fmaf(v1.w, f1.w, d);
        d = fmaf(v2.x, f2.x, d); d = fmaf(v2.y, f2.y, d); d = fmaf(v2.z, f2.z, d); d = fmaf(v2.w, f2.w, d);
        d = fmaf(v3.x, f3.x, d); d = fmaf(v3.y, f3.y, d); d = fmaf(v3.z, f3.z, d); d = fmaf(v3.w, f3.w, d);
#pragma unroll
        for (int o = 16; o > 0; o >>= 1)
            d += __shfl_xor_sync(0xffffffffu, d, o);

        // online softmax update (d is warp-uniform -> no divergence)
        if (d > m) {
            const float sc = __expf(m - d);  // exp(-inf)=0 handled on first row
            l *= sc;
            a0.x *= sc; a0.y *= sc; a0.z *= sc; a0.w *= sc;
            a1.x *= sc; a1.y *= sc; a1.z *= sc; a1.w *= sc;
            a2.x *= sc; a2.y *= sc; a2.z *= sc; a2.w *= sc;
            a3.x *= sc; a3.y *= sc; a3.z *= sc; a3.w *= sc;
            m = d;
        }
        const float wgt = __expf(d - m);
        l += wgt;
        a0.x = fmaf(wgt, v0.x, a0.x); a0.y = fmaf(wgt, v0.y, a0.y);
        a0.z = fmaf(wgt, v0.z, a0.z); a0.w = fmaf(wgt, v0.w, a0.w);
        a1.x = fmaf(wgt, v1.x, a1.x); a1.y = fmaf(wgt, v1.y, a1.y);
        a1.z = fmaf(wgt, v1.z, a1.z); a1.w = fmaf(wgt, v1.w, a1.w);
        a2.x = fmaf(wgt, v2.x, a2.x); a2.y = fmaf(wgt, v2.y, a2.y);
        a2.z = fmaf(wgt, v2.z, a2.z); a2.w = fmaf(wgt, v2.w, a2.w);
        a3.x = fmaf(wgt, v3.x, a3.x); a3.y = fmaf(wgt, v3.y, a3.y);
        a3.z = fmaf(wgt, v3.z, a3.z); a3.w = fmaf(wgt, v3.w, a3.w);
    }

    // Stash per-warp partials in shared
    if (lane == 0) { sm_m[w] = m; sm_l[w] = l; }
    sm_acc[w][lane]      = a0;
    sm_acc[w][lane + 32] = a1;
    sm_acc[w][lane + 64] = a2;
    sm_acc[w][lane + 96] = a3;
    __syncthreads();

    // Block combine: 8 warps -> one partial (M, L, ctx[512])
    float M = sm_m[0];
#pragma unroll
    for (int i = 1; i < WARPS; i++) M = fmaxf(M, sm_m[i]);

    float ef[WARPS];
    float L = 0.f;
#pragma unroll
    for (int i = 0; i < WARPS; i++) {
        ef[i] = __expf(sm_m[i] - M);
        L = fmaf(ef[i], sm_l[i], L);
    }

    const float* accf = reinterpret_cast<const float*>(sm_acc); // [WARPS][512]
    const int pidx = b * NSPLIT + split;
    float* pc = g_pC + (size_t)pidx * DXE;
#pragma unroll
    for (int half = 0; half < 2; half++) {
        const int d = t + half * 256;
        float c = 0.f;
#pragma unroll
        for (int i = 0; i < WARPS; i++)
            c = fmaf(ef[i], accf[i * DXE + d], c);
        pc[d] = c;
    }
    if (t == 0) { g_pM[pidx] = M; g_pL[pidx] = L; }

    // ---- fused final reduce: last CTA per batch combines all partials ----
    __syncthreads();             // all partial STGs issued block-wide
    if (t == 0) {
        __threadfence();         // release this CTA's partial
        const unsigned int prev = atomicAdd(&g_cnt[b], 1u);
        s_last = (prev == NSPLIT - 1) ? 1 : 0;
    }
    __syncthreads();
    if (!s_last) return;

    __threadfence();             // acquire: all other CTAs' partials visible

    __shared__ float rM[NSPLIT];
    __shared__ float rL[NSPLIT];
    if (t < NSPLIT) {
        rM[t] = g_pM[b * NSPLIT + t];
        rL[t] = g_pL[b * NSPLIT + t];
    }

    // issue 16 independent per-dim partial loads (L2-hot)
    float cv0[NSPLIT], cv1[NSPLIT];
#pragma unroll
    for (int i = 0; i < NSPLIT; i++) {
        const float* pci = g_pC + (size_t)(b * NSPLIT + i) * DXE;
        cv0[i] = pci[t];
        cv1[i] = pci[t + 256];
    }
    __syncthreads();

    float GM = rM[0];
#pragma unroll
    for (int i = 1; i < NSPLIT; i++) GM = fmaxf(GM, rM[i]);

    float GL = 0.f, c0 = 0.f, c1 = 0.f;
#pragma unroll
    for (int i = 0; i < NSPLIT; i++) {
        const float e = __expf(rM[i] - GM);
        GL = fmaf(e, rL[i], GL);
        c0 = fmaf(e, cv0[i], c0);
        c1 = fmaf(e, cv1[i], c1);
    }
    const float inv = 1.f / GL;
    out[b * DXE + t]       = c0 * inv;
    out[b * DXE + t + 256] = c1 * inv;

    if (t == 0) g_cnt[b] = 0;    // reset for next graph replay
}

// ---------------------------------------------------------------------------
static inline void launch_pdl(const void* func, dim3 grid, dim3 block,
                              void** args)
{
    cudaLaunchConfig_t cfg = {};
    cfg.gridDim = grid;
    cfg.blockDim = block;
    cfg.dynamicSmemBytes = 0;
    cfg.stream = 0;            // default stream (captured by harness)
    cudaLaunchAttribute attr[1];
    attr[0].id = cudaLaunchAttributeProgrammaticStreamSerialization;
    attr[0].val.programmaticStreamSerializationAllowed = 1;
    cfg.attrs = attr;
    cfg.numAttrs = 1;
    cudaLaunchKernelExC(&cfg, func, args);
}

extern "C" void kernel_launch(void* const* d_in, const int* in_sizes, int n_in,
                              void* d_out, int out_size)
{
    const float* x  = (const float*)d_in[0];  // [64, 4096, 512]
    const float* qm = (const float*)d_in[1];  // [64, 128, 512]
    const float* W  = (const float*)d_in[2];  // [512, 512]
    const float* p  = (const float*)d_in[3];  // [128, 1]
    float* out = (float*)d_out;               // [64, 512]

    // A1: plain launch
    newq_kernel<<<(QSPLIT * BB * (DQE / 4)) / 256, 256>>>(qm, p);

    // A2: PDL-overlapped with A1's tail
    {
        void* args[] = { (void*)&W };
        launch_pdl((const void*)first_kernel,
                   dim3(KSPLIT, BB / BGRP), dim3(512), args);
    }

    // B: PDL-overlapped with A2's tail
    {
        void* args[] = { (void*)&x, (void*)&out };
        launch_pdl((const void*)attn_partial_kernel,
                   dim3(NSPLIT, BB), dim3(TPB), args);
    }
}

// round 14
// speedup vs baseline: 1.0212x; 1.0003x over previous
#include <cuda_runtime.h>
#include <math.h>

// Problem shape (fixed by the dataset)
#define BB 64
#define SS 4096
#define DXE 512
#define QQ 128
#define DQE 512

#define NSPLIT 16
#define ROWS_PER_SPLIT (SS / NSPLIT)   // 256
#define TPB 256
#define WARPS (TPB / 32)               // 8
#define ROWS_PER_WARP (ROWS_PER_SPLIT / WARPS) // 32

#define KSPLIT 8
#define KCHUNK (DQE / KSPLIT)          // 64

#define QSPLIT 16
#define QC (QQ / QSPLIT)               // 8

#define BGRP 2                         // batches per first_kernel CTA

// Scratch (allocation-free: __device__ globals)
__device__ float g_newq_part[QSPLIT][BB * DQE];
__device__ float g_first_part[KSPLIT][BB * DXE];
__device__ float g_pM[BB * NSPLIT];
__device__ float g_pL[BB * NSPLIT];
__device__ float g_pC[BB * NSPLIT * DXE];
__device__ unsigned int g_cnt[BB];     // zero-init; reset by last CTA each pass

// ---------------------------------------------------------------------------
// Kernel A1: new_q partials, maximal parallelism. (measured ~6.5us)
// ---------------------------------------------------------------------------
__global__ __launch_bounds__(256) void newq_kernel(
    const float* __restrict__ qm,   // [B, Q, DQ]
    const float* __restrict__ p)    // [Q, 1]
{
    const int idx = blockIdx.x * 256 + threadIdx.x; // 0..131071
    const int c   = idx >> 13;                      // Q-chunk 0..15
    const int rem = idx & 8191;
    const int b   = rem >> 7;                       // batch 0..63
    const int d4  = rem & 127;                      // float4 index 0..127

    const float4* qb = reinterpret_cast<const float4*>(
        qm + (size_t)b * QQ * DQE + (size_t)(c * QC) * DQE) + d4;
    const float* pc = p + c * QC;

    const float4 v0 = qb[0 * (DQE / 4)];
    const float4 v1 = qb[1 * (DQE / 4)];
    const float4 v2 = qb[2 * (DQE / 4)];
    const float4 v3 = qb[3 * (DQE / 4)];
    const float4 v4 = qb[4 * (DQE / 4)];
    const float4 v5 = qb[5 * (DQE / 4)];
    const float4 v6 = qb[6 * (DQE / 4)];
    const float4 v7 = qb[7 * (DQE / 4)];
    const float s0 = __ldg(&pc[0]);
    const float s1 = __ldg(&pc[1]);
    const float s2 = __ldg(&pc[2]);
    const float s3 = __ldg(&pc[3]);
    const float s4 = __ldg(&pc[4]);
    const float s5 = __ldg(&pc[5]);
    const float s6 = __ldg(&pc[6]);
    const float s7 = __ldg(&pc[7]);

    float4 r;
    r.x = fmaf(v0.x, s0, v1.x * s1); r.x = fmaf(v2.x, s2, r.x); r.x = fmaf(v3.x, s3, r.x);
    r.x = fmaf(v4.x, s4, r.x); r.x = fmaf(v5.x, s5, r.x); r.x = fmaf(v6.x, s6, r.x); r.x = fmaf(v7.x, s7, r.x);
    r.y = fmaf(v0.y, s0, v1.y * s1); r.y = fmaf(v2.y, s2, r.y); r.y = fmaf(v3.y, s3, r.y);
    r.y = fmaf(v4.y, s4, r.y); r.y = fmaf(v5.y, s5, r.y); r.y = fmaf(v6.y, s6, r.y); r.y = fmaf(v7.y, s7, r.y);
    r.z = fmaf(v0.z, s0, v1.z * s1); r.z = fmaf(v2.z, s2, r.z); r.z = fmaf(v3.z, s3, r.z);
    r.z = fmaf(v4.z, s4, r.z); r.z = fmaf(v5.z, s5, r.z); r.z = fmaf(v6.z, s6, r.z); r.z = fmaf(v7.z, s7, r.z);
    r.w = fmaf(v0.w, s0, v1.w * s1); r.w = fmaf(v2.w, s2, r.w); r.w = fmaf(v3.w, s3, r.w);
    r.w = fmaf(v4.w, s4, r.w); r.w = fmaf(v5.w, s5, r.w); r.w = fmaf(v6.w, s6, r.w); r.w = fmaf(v7.w, s7, r.w);

    reinterpret_cast<float4*>(&g_newq_part[c][b * DQE])[d4] = r;

    cudaTriggerProgrammaticLaunchCompletion();
}

// ---------------------------------------------------------------------------
// Kernel A2 (v3): first_part[kc][b,t] = sum_{d in chunk kc} new_q[b,d]*W[d,t]
// grid = (8, 32) = 256 CTAs x 512 thr. PDL consumer of newq.
// ---------------------------------------------------------------------------
__global__ __launch_bounds__(512) void first_kernel(
    const float* __restrict__ W)    // [DQ, DX]
{
    const int kc = blockIdx.x;      // 0..7
    const int bg = blockIdx.y;      // 0..31
    const int t  = threadIdx.x;     // 0..511

    __shared__ float sq[BGRP][KCHUNK];

    cudaGridDependencySynchronize();

    if (t < BGRP * KCHUNK) {
        const int j = t >> 6;           // batch within group
        const int d = t & 63;
        const int off = (bg * BGRP + j) * DQE + kc * KCHUNK + d;
        float acc[QSPLIT];
#pragma unroll
        for (int c = 0; c < QSPLIT; c++) acc[c] = g_newq_part[c][off];
        float s = 0.f;
#pragma unroll
        for (int c = 0; c < QSPLIT; c++) s += acc[c];
        sq[j][d] = s;
    }
    __syncthreads();

    float acc0 = 0.f, acc1 = 0.f;
    const float* Wc = W + (size_t)(kc * KCHUNK) * DXE + t;
#pragma unroll 16
    for (int d = 0; d < KCHUNK; d++) {
        const float w = Wc[d * DXE];
        acc0 = fmaf(sq[0][d], w, acc0);
        acc1 = fmaf(sq[1][d], w, acc1);
    }
    g_first_part[kc][(bg * BGRP + 0) * DXE + t] = acc0;
    g_first_part[kc][(bg * BGRP + 1) * DXE + t] = acc1;

    cudaTriggerProgrammaticLaunchCompletion();
}

// ---------------------------------------------------------------------------
// Kernel B: fused flash pass + fused last-CTA final reduce.
// PDL consumer of first_kernel — but x loads are INDEPENDENT of first, so
// row 0 is prefetched BEFORE the grid-dependency sync (overlaps first_kernel's
// drain with the flash pass's memory ramp).
// grid = (NSPLIT, B), block = 256.
// ---------------------------------------------------------------------------
__global__ __launch_bounds__(TPB, 4) void attn_partial_kernel(
    const float* __restrict__ x,   // [B, S, DX]
    float* __restrict__ out)       // [B, DX]
{
    const int split = blockIdx.x;
    const int b     = blockIdx.y;
    const int t     = threadIdx.x;
    const int w     = t >> 5;
    const int lane  = t & 31;

    __shared__ float sfirst[DXE];
    __shared__ float sm_m[WARPS];
    __shared__ float sm_l[WARPS];
    __shared__ float4 sm_acc[WARPS][DXE / 4];
    __shared__ int s_last;

    const float4* xb = reinterpret_cast<const float4*>(
        x + (size_t)b * SS * DXE);
    const int s0 = split * ROWS_PER_SPLIT + w;

    // --- prefetch row 0 BEFORE the dependency sync (x doesn't depend on it)
    const float4* xr0 = xb + (size_t)s0 * (DXE / 4);
    float4 pv0 = xr0[lane];
    float4 pv1 = xr0[lane + 32];
    float4 pv2 = xr0[lane + 64];
    float4 pv3 = xr0[lane + 96];

    // wait for first_kernel's grid (PDL)
    cudaGridDependencySynchronize();

    // sum the 8 split-K partials of `first`
#pragma unroll
    for (int half = 0; half < 2; half++) {
        const int d = t + half * 256;
        float f = 0.f;
#pragma unroll
        for (int kc = 0; kc < KSPLIT; kc++)
            f += g_first_part[kc][b * DXE + d];
        sfirst[d] = f;
    }
    __syncthreads();

    // Per-lane slice of first (as float4, strided by 32 lanes)
    const float4* sf4 = reinterpret_cast<const float4*>(sfirst);
    const float4 f0 = sf4[lane];
    const float4 f1 = sf4[lane + 32];
    const float4 f2 = sf4[lane + 64];
    const float4 f3 = sf4[lane + 96];

    // --- peeled iteration 0 using the prefetched row: m=d, l=1, a=v
    float m, l;
    float4 a0, a1, a2, a3;
    {
        float d;
        d = pv0.x * f0.x;
        d = fmaf(pv0.y, f0.y, d); d = fmaf(pv0.z, f0.z, d); d = fmaf(pv0.w, f0.w, d);
        d = fmaf(pv1.x, f1.x, d); d = fmaf(pv1.y, f1.y, d); d = fmaf(pv1.z, f1.z, d); d = fmaf(pv1.w, f1.w, d);
        d = fmaf(pv2.x, f2.x, d); d = fmaf(pv2.y, f2.y, d); d = fmaf(pv2.z, f2.z, d); d = fmaf(pv2.w, f2.w, d);
        d = fmaf(pv3.x, f3.x, d); d = fmaf(pv3.y, f3.y, d); d = fmaf(pv3.z, f3.z, d); d = fmaf(pv3.w, f3.w, d);
#pragma unroll
        for (int o = 16; o > 0; o >>= 1)
            d += __shfl_xor_sync(0xffffffffu, d, o);
        m = d;
        l = 1.f;
        a0 = pv0; a1 = pv1; a2 = pv2; a3 = pv3;
    }

    for (int r = 1; r < ROWS_PER_WARP; r++) {
        const int s = s0 + WARPS * r;
        const float4* xr = xb + (size_t)s * (DXE / 4);
        // 4 independent LDG.128 per lane -> MLP = 4
        const float4 v0 = xr[lane];
        const float4 v1 = xr[lane + 32];
        const float4 v2 = xr[lane + 64];
        const float4 v3 = xr[lane + 96];

        // dot(first, x_row)
        float d;
        d = v0.x * f0.x;
        d = fmaf(v0.y, f0.y, d); d = fmaf(v0.z, f0.z, d); d = fmaf(v0.w, f0.w, d);
        d = fmaf(v1.x, f1.x, d); d = fmaf(v1.y, f1.y, d); d = fmaf(v1.z, f1.z, d); d = fmaf(v1.w, f1.w, d);
        d = fmaf(v2.x, f2.x, d); d = fmaf(v2.y, f2.y, d); d = fmaf(v2.z, f2.z, d); d = fmaf(v2.w, f2.w, d);
        d = fmaf(v3.x, f3.x, d); d = fmaf(v3.y, f3.y, d); d = fmaf(v3.z, f3.z, d); d = fmaf(v3.w, f3.w, d);
#pragma unroll
        for (int o = 16; o > 0; o >>= 1)
            d += __shfl_xor_sync(0xffffffffu, d, o);

        // online softmax update (d is warp-uniform -> no divergence)
        if (d > m) {
            const float sc = __expf(m - d);
            l *= sc;
            a0.x *= sc; a0.y *= sc; a0.z *= sc; a0.w *= sc;
            a1.x *= sc; a1.y *= sc; a1.z *= sc; a1.w *= sc;
            a2.x *= sc; a2.y *= sc; a2.z *= sc; a2.w *= sc;
            a3.x *= sc; a3.y *= sc; a3.z *= sc; a3.w *= sc;
            m = d;
        }
        const float wgt = __expf(d - m);
        l += wgt;
        a0.x = fmaf(wgt, v0.x, a0.x); a0.y = fmaf(wgt, v0.y, a0.y);
        a0.z = fmaf(wgt, v0.z, a0.z); a0.w = fmaf(wgt, v0.w, a0.w);
        a1.x = fmaf(wgt, v1.x, a1.x); a1.y = fmaf(wgt, v1.y, a1.y);
        a1.z = fmaf(wgt, v1.z, a1.z); a1.w = fmaf(wgt, v1.w, a1.w);
        a2.x = fmaf(wgt, v2.x, a2.x); a2.y = fmaf(wgt, v2.y, a2.y);
        a2.z = fmaf(wgt, v2.z, a2.z); a2.w = fmaf(wgt, v2.w, a2.w);
        a3.x = fmaf(wgt, v3.x, a3.x); a3.y = fmaf(wgt, v3.y, a3.y);
        a3.z = fmaf(wgt, v3.z, a3.z); a3.w = fmaf(wgt, v3.w, a3.w);
    }

    // Stash per-warp partials in shared
    if (lane == 0) { sm_m[w] = m; sm_l[w] = l; }
    sm_acc[w][lane]      = a0;
    sm_acc[w][lane + 32] = a1;
    sm_acc[w][lane + 64] = a2;
    sm_acc[w][lane + 96] = a3;
    __syncthreads();

    // Block combine: 8 warps -> one partial (M, L, ctx[512])
    float M = sm_m[0];
#pragma unroll
    for (int i = 1; i < WARPS; i++) M = fmaxf(M, sm_m[i]);

    float ef[WARPS];
    float L = 0.f;
#pragma unroll
    for (int i = 0; i < WARPS; i++) {
        ef[i] = __expf(sm_m[i] - M);
        L = fmaf(ef[i], sm_l[i], L);
    }

    const float* accf = reinterpret_cast<const float*>(sm_acc); // [WARPS][512]
    const int pidx = b * NSPLIT + split;
    float* pc = g_pC + (size_t)pidx * DXE;
#pragma unroll
    for (int half = 0; half < 2; half++) {
        const int d = t + half * 256;
        float c = 0.f;
#pragma unroll
        for (int i = 0; i < WARPS; i++)
            c = fmaf(ef[i], accf[i * DXE + d], c);
        pc[d] = c;
    }
    if (t == 0) { g_pM[pidx] = M; g_pL[pidx] = L; }

    // ---- fused final reduce: last CTA per batch combines all partials ----
    __syncthreads();
    if (t == 0) {
        __threadfence();
        const unsigned int prev = atomicAdd(&g_cnt[b], 1u);
        s_last = (prev == NSPLIT - 1) ? 1 : 0;
    }
    __syncthreads();
    if (!s_last) return;

    __threadfence();

    __shared__ float rM[NSPLIT];
    __shared__ float rL[NSPLIT];
    if (t < NSPLIT) {
        rM[t] = g_pM[b * NSPLIT + t];
        rL[t] = g_pL[b * NSPLIT + t];
    }

    float cv0[NSPLIT], cv1[NSPLIT];
#pragma unroll
    for (int i = 0; i < NSPLIT; i++) {
        const float* pci = g_pC + (size_t)(b * NSPLIT + i) * DXE;
        cv0[i] = pci[t];
        cv1[i] = pci[t + 256];
    }
    __syncthreads();

    float GM = rM[0];
#pragma unroll
    for (int i = 1; i < NSPLIT; i++) GM = fmaxf(GM, rM[i]);

    float GL = 0.f, c0 = 0.f, c1 = 0.f;
#pragma unroll
    for (int i = 0; i < NSPLIT; i++) {
        const float e = __expf(rM[i] - GM);
        GL = fmaf(e, rL[i], GL);
        c0 = fmaf(e, cv0[i], c0);
        c1 = fmaf(e, cv1[i], c1);
    }
    const float inv = 1.f / GL;
    out[b * DXE + t]       = c0 * inv;
    out[b * DXE + t + 256] = c1 * inv;

    if (t == 0) g_cnt[b] = 0;    // reset for next graph replay
}

// ---------------------------------------------------------------------------
static inline void launch_pdl(const void* func, dim3 grid, dim3 block,
                              void** args)
{
    cudaLaunchConfig_t cfg = {};
    cfg.gridDim = grid;
    cfg.blockDim = block;
    cfg.dynamicSmemBytes = 0;
    cfg.stream = 0;            // default stream (captured by harness)
    cudaLaunchAttribute attr[1];
    attr[0].id = cudaLaunchAttributeProgrammaticStreamSerialization;
    attr[0].val.programmaticStreamSerializationAllowed = 1;
    cfg.attrs = attr;
    cfg.numAttrs = 1;
    cudaLaunchKernelExC(&cfg, func, args);
}

extern "C" void kernel_launch(void* const* d_in, const int* in_sizes, int n_in,
                              void* d_out, int out_size)
{
    const float* x  = (const float*)d_in[0];  // [64, 4096, 512]
    const float* qm = (const float*)d_in[1];  // [64, 128, 512]
    const float* W  = (const float*)d_in[2];  // [512, 512]
    const float* p  = (const float*)d_in[3];  // [128, 1]
    float* out = (float*)d_out;               // [64, 512]

    // A1: plain launch
    newq_kernel<<<(QSPLIT * BB * (DQE / 4)) / 256, 256>>>(qm, p);

    // A2: PDL-overlapped with A1's tail
    {
        void* args[] = { (void*)&W };
        launch_pdl((const void*)first_kernel,
                   dim3(KSPLIT, BB / BGRP), dim3(512), args);
    }

    // B: PDL-overlapped with A2 (x prefetch runs during A2's drain)
    {
        void* args[] = { (void*)&x, (void*)&out };
        launch_pdl((const void*)attn_partial_kernel,
                   dim3(NSPLIT, BB), dim3(TPB), args);
    }
}

// round 15
// speedup vs baseline: 1.0219x; 1.0007x over previous
#include <cuda_runtime.h>
#include <math.h>

// Problem shape (fixed by the dataset)
#define BB 64
#define SS 4096
#define DXE 512
#define QQ 128
#define DQE 512

#define NSPLIT 16
#define ROWS_PER_SPLIT (SS / NSPLIT)   // 256
#define TPB 256
#define WARPS (TPB / 32)               // 8
#define ROWS_PER_WARP (ROWS_PER_SPLIT / WARPS) // 32

#define KSPLIT 8
#define KCHUNK (DQE / KSPLIT)          // 64

#define QSPLIT 32
#define QC (QQ / QSPLIT)               // 4

#define BGRP 2                         // batches per first_kernel CTA

// Scratch (allocation-free: __device__ globals)
__device__ float g_newq_part[QSPLIT][BB * DQE];
__device__ float g_first_part[KSPLIT][BB * DXE];
__device__ float g_pM[BB * NSPLIT];
__device__ float g_pL[BB * NSPLIT];
__device__ float g_pC[BB * NSPLIT * DXE];
__device__ unsigned int g_cnt[BB];     // zero-init; reset by last CTA each pass

// ---------------------------------------------------------------------------
// Kernel A1: new_q partials. QSPLIT=32 -> 4 float4 loads/thread: 16 data regs
// + addresses fit the 32-reg budget, so all 4 loads are truly in flight
// (R14 profile showed regs=32 serialized the 8-load version).
// 262144 threads (1024 CTAs x 256).
// ---------------------------------------------------------------------------
__global__ __launch_bounds__(256) void newq_kernel(
    const float* __restrict__ qm,   // [B, Q, DQ]
    const float* __restrict__ p)    // [Q, 1]
{
    const int idx = blockIdx.x * 256 + threadIdx.x; // 0..262143
    const int c   = idx >> 13;                      // Q-chunk 0..31
    const int rem = idx & 8191;
    const int b   = rem >> 7;                       // batch 0..63
    const int d4  = rem & 127;                      // float4 index 0..127

    const float4* qb = reinterpret_cast<const float4*>(
        qm + (size_t)b * QQ * DQE + (size_t)(c * QC) * DQE) + d4;
    const float* pc = p + c * QC;

    const float4 v0 = qb[0 * (DQE / 4)];
    const float4 v1 = qb[1 * (DQE / 4)];
    const float4 v2 = qb[2 * (DQE / 4)];
    const float4 v3 = qb[3 * (DQE / 4)];
    const float s0 = __ldg(&pc[0]);
    const float s1 = __ldg(&pc[1]);
    const float s2 = __ldg(&pc[2]);
    const float s3 = __ldg(&pc[3]);

    float4 r;
    r.x = fmaf(v0.x, s0, v1.x * s1);
    r.x = fmaf(v2.x, s2, r.x); r.x = fmaf(v3.x, s3, r.x);
    r.y = fmaf(v0.y, s0, v1.y * s1);
    r.y = fmaf(v2.y, s2, r.y); r.y = fmaf(v3.y, s3, r.y);
    r.z = fmaf(v0.z, s0, v1.z * s1);
    r.z = fmaf(v2.z, s2, r.z); r.z = fmaf(v3.z, s3, r.z);
    r.w = fmaf(v0.w, s0, v1.w * s1);
    r.w = fmaf(v2.w, s2, r.w); r.w = fmaf(v3.w, s3, r.w);

    reinterpret_cast<float4*>(&g_newq_part[c][b * DQE])[d4] = r;

    cudaTriggerProgrammaticLaunchCompletion();
}

// ---------------------------------------------------------------------------
// Kernel A2: first_part[kc][b,t] = sum_{d in chunk kc} new_q[b,d]*W[d,t]
// grid = (8, 32) = 256 CTAs x 512 thr. PDL consumer of newq. Stage-1 sums
// 32 independent partial loads (unrolled -> latency-hidden).
// ---------------------------------------------------------------------------
__global__ __launch_bounds__(512) void first_kernel(
    const float* __restrict__ W)    // [DQ, DX]
{
    const int kc = blockIdx.x;      // 0..7
    const int bg = blockIdx.y;      // 0..31
    const int t  = threadIdx.x;     // 0..511

    __shared__ float sq[BGRP][KCHUNK];

    cudaGridDependencySynchronize();

    if (t < BGRP * KCHUNK) {
        const int j = t >> 6;           // batch within group
        const int d = t & 63;
        const int off = (bg * BGRP + j) * DQE + kc * KCHUNK + d;
        float acc[QSPLIT];
#pragma unroll
        for (int c = 0; c < QSPLIT; c++) acc[c] = g_newq_part[c][off];
        float s = 0.f;
#pragma unroll
        for (int c = 0; c < QSPLIT; c++) s += acc[c];
        sq[j][d] = s;
    }
    __syncthreads();

    float acc0 = 0.f, acc1 = 0.f;
    const float* Wc = W + (size_t)(kc * KCHUNK) * DXE + t;
#pragma unroll 16
    for (int d = 0; d < KCHUNK; d++) {
        const float w = Wc[d * DXE];
        acc0 = fmaf(sq[0][d], w, acc0);
        acc1 = fmaf(sq[1][d], w, acc1);
    }
    g_first_part[kc][(bg * BGRP + 0) * DXE + t] = acc0;
    g_first_part[kc][(bg * BGRP + 1) * DXE + t] = acc1;

    cudaTriggerProgrammaticLaunchCompletion();
}

// ---------------------------------------------------------------------------
// Kernel B: fused flash pass + fused last-CTA final reduce. (R14 form)
// grid = (NSPLIT, B), block = 256.
// ---------------------------------------------------------------------------
__global__ __launch_bounds__(TPB, 4) void attn_partial_kernel(
    const float* __restrict__ x,   // [B, S, DX]
    float* __restrict__ out)       // [B, DX]
{
    const int split = blockIdx.x;
    const int b     = blockIdx.y;
    const int t     = threadIdx.x;
    const int w     = t >> 5;
    const int lane  = t & 31;

    __shared__ float sfirst[DXE];
    __shared__ float sm_m[WARPS];
    __shared__ float sm_l[WARPS];
    __shared__ float4 sm_acc[WARPS][DXE / 4];
    __shared__ int s_last;

    const float4* xb = reinterpret_cast<const float4*>(
        x + (size_t)b * SS * DXE);
    const int s0 = split * ROWS_PER_SPLIT + w;

    // --- prefetch row 0 BEFORE the dependency sync (x doesn't depend on it)
    const float4* xr0 = xb + (size_t)s0 * (DXE / 4);
    float4 pv0 = xr0[lane];
    float4 pv1 = xr0[lane + 32];
    float4 pv2 = xr0[lane + 64];
    float4 pv3 = xr0[lane + 96];

    // wait for first_kernel's grid (PDL)
    cudaGridDependencySynchronize();

    // sum the 8 split-K partials of `first`
#pragma unroll
    for (int half = 0; half < 2; half++) {
        const int d = t + half * 256;
        float f = 0.f;
#pragma unroll
        for (int kc = 0; kc < KSPLIT; kc++)
            f += g_first_part[kc][b * DXE + d];
        sfirst[d] = f;
    }
    __syncthreads();

    // Per-lane slice of first (as float4, strided by 32 lanes)
    const float4* sf4 = reinterpret_cast<const float4*>(sfirst);
    const float4 f0 = sf4[lane];
    const float4 f1 = sf4[lane + 32];
    const float4 f2 = sf4[lane + 64];
    const float4 f3 = sf4[lane + 96];

    // --- peeled iteration 0 using the prefetched row: m=d, l=1, a=v
    float m, l;
    float4 a0, a1, a2, a3;
    {
        float d;
        d = pv0.x * f0.x;
        d = fmaf(pv0.y, f0.y, d); d = fmaf(pv0.z, f0.z, d); d = fmaf(pv0.w, f0.w, d);
        d = fmaf(pv1.x, f1.x, d); d = fmaf(pv1.y, f1.y, d); d = fmaf(pv1.z, f1.z, d); d = fmaf(pv1.w, f1.w, d);
        d = fmaf(pv2.x, f2.x, d); d = fmaf(pv2.y, f2.y, d); d = fmaf(pv2.z, f2.z, d); d = fmaf(pv2.w, f2.w, d);
        d = fmaf(pv3.x, f3.x, d); d = fmaf(pv3.y, f3.y, d); d = fmaf(pv3.z, f3.z, d); d = fmaf(pv3.w, f3.w, d);
#pragma unroll
        for (int o = 16; o > 0; o >>= 1)
            d += __shfl_xor_sync(0xffffffffu, d, o);
        m = d;
        l = 1.f;
        a0 = pv0; a1 = pv1; a2 = pv2; a3 = pv3;
    }

    for (int r = 1; r < ROWS_PER_WARP; r++) {
        const int s = s0 + WARPS * r;
        const float4* xr = xb + (size_t)s * (DXE / 4);
        // 4 independent LDG.128 per lane -> MLP = 4
        const float4 v0 = xr[lane];
        const float4 v1 = xr[lane + 32];
        const float4 v2 = xr[lane + 64];
        const float4 v3 = xr[lane + 96];

        // dot(first, x_row)
        float d;
        d = v0.x * f0.x;
        d = fmaf(v0.y, f0.y, d); d = fmaf(v0.z, f0.z, d); d = fmaf(v0.w, f0.w, d);
        d = fmaf(v1.x, f1.x, d); d = fmaf(v1.y, f1.y, d); d = fmaf(v1.z, f1.z, d); d = fmaf(v1.w, f1.w, d);
        d = fmaf(v2.x, f2.x, d); d = fmaf(v2.y, f2.y, d); d = fmaf(v2.z, f2.z, d); d = fmaf(v2.w, f2.w, d);
        d = fmaf(v3.x, f3.x, d); d = fmaf(v3.y, f3.y, d); d = fmaf(v3.z, f3.z, d); d = fmaf(v3.w, f3.w, d);
#pragma unroll
        for (int o = 16; o > 0; o >>= 1)
            d += __shfl_xor_sync(0xffffffffu, d, o);

        // online softmax update (d is warp-uniform -> no divergence)
        if (d > m) {
            const float sc = __expf(m - d);
            l *= sc;
            a0.x *= sc; a0.y *= sc; a0.z *= sc; a0.w *= sc;
            a1.x *= sc; a1.y *= sc; a1.z *= sc; a1.w *= sc;
            a2.x *= sc; a2.y *= sc; a2.z *= sc; a2.w *= sc;
            a3.x *= sc; a3.y *= sc; a3.z *= sc; a3.w *= sc;
            m = d;
        }
        const float wgt = __expf(d - m);
        l += wgt;
        a0.x = fmaf(wgt, v0.x, a0.x); a0.y = fmaf(wgt, v0.y, a0.y);
        a0.z = fmaf(wgt, v0.z, a0.z); a0.w = fmaf(wgt, v0.w, a0.w);
        a1.x = fmaf(wgt, v1.x, a1.x); a1.y = fmaf(wgt, v1.y, a1.y);
        a1.z = fmaf(wgt, v1.z, a1.z); a1.w = fmaf(wgt, v1.w, a1.w);
        a2.x = fmaf(wgt, v2.x, a2.x); a2.y = fmaf(wgt, v2.y, a2.y);
        a2.z = fmaf(wgt, v2.z, a2.z); a2.w = fmaf(wgt, v2.w, a2.w);
        a3.x = fmaf(wgt, v3.x, a3.x); a3.y = fmaf(wgt, v3.y, a3.y);
        a3.z = fmaf(wgt, v3.z, a3.z); a3.w = fmaf(wgt, v3.w, a3.w);
    }

    // Stash per-warp partials in shared
    if (lane == 0) { sm_m[w] = m; sm_l[w] = l; }
    sm_acc[w][lane]      = a0;
    sm_acc[w][lane + 32] = a1;
    sm_acc[w][lane + 64] = a2;
    sm_acc[w][lane + 96] = a3;
    __syncthreads();

    // Block combine: 8 warps -> one partial (M, L, ctx[512])
    float M = sm_m[0];
#pragma unroll
    for (int i = 1; i < WARPS; i++) M = fmaxf(M, sm_m[i]);

    float ef[WARPS];
    float L = 0.f;
#pragma unroll
    for (int i = 0; i < WARPS; i++) {
        ef[i] = __expf(sm_m[i] - M);
        L = fmaf(ef[i], sm_l[i], L);
    }

    const float* accf = reinterpret_cast<const float*>(sm_acc); // [WARPS][512]
    const int pidx = b * NSPLIT + split;
    float* pc = g_pC + (size_t)pidx * DXE;
#pragma unroll
    for (int half = 0; half < 2; half++) {
        const int d = t + half * 256;
        float c = 0.f;
#pragma unroll
        for (int i = 0; i < WARPS; i++)
            c = fmaf(ef[i], accf[i * DXE + d], c);
        pc[d] = c;
    }
    if (t == 0) { g_pM[pidx] = M; g_pL[pidx] = L; }

    // ---- fused final reduce: last CTA per batch combines all partials ----
    __syncthreads();
    if (t == 0) {
        __threadfence();
        const unsigned int prev = atomicAdd(&g_cnt[b], 1u);
        s_last = (prev == NSPLIT - 1) ? 1 : 0;
    }
    __syncthreads();
    if (!s_last) return;

    __threadfence();

    __shared__ float rM[NSPLIT];
    __shared__ float rL[NSPLIT];
    if (t < NSPLIT) {
        rM[t] = g_pM[b * NSPLIT + t];
        rL[t] = g_pL[b * NSPLIT + t];
    }

    float cv0[NSPLIT], cv1[NSPLIT];
#pragma unroll
    for (int i = 0; i < NSPLIT; i++) {
        const float* pci = g_pC + (size_t)(b * NSPLIT + i) * DXE;
        cv0[i] = pci[t];
        cv1[i] = pci[t + 256];
    }
    __syncthreads();

    float GM = rM[0];
#pragma unroll
    for (int i = 1; i < NSPLIT; i++) GM = fmaxf(GM, rM[i]);

    float GL = 0.f, c0 = 0.f, c1 = 0.f;
#pragma unroll
    for (int i = 0; i < NSPLIT; i++) {
        const float e = __expf(rM[i] - GM);
        GL = fmaf(e, rL[i], GL);
        c0 = fmaf(e, cv0[i], c0);
        c1 = fmaf(e, cv1[i], c1);
    }
    const float inv = 1.f / GL;
    out[b * DXE + t]       = c0 * inv;
    out[b * DXE + t + 256] = c1 * inv;

    if (t == 0) g_cnt[b] = 0;    // reset for next graph replay
}

// ---------------------------------------------------------------------------
static inline void launch_pdl(const void* func, dim3 grid, dim3 block,
                              void** args)
{
    cudaLaunchConfig_t cfg = {};
    cfg.gridDim = grid;
    cfg.blockDim = block;
    cfg.dynamicSmemBytes = 0;
    cfg.stream = 0;            // default stream (captured by harness)
    cudaLaunchAttribute attr[1];
    attr[0].id = cudaLaunchAttributeProgrammaticStreamSerialization;
    attr[0].val.programmaticStreamSerializationAllowed = 1;
    cfg.attrs = attr;
    cfg.numAttrs = 1;
    cudaLaunchKernelExC(&cfg, func, args);
}

extern "C" void kernel_launch(void* const* d_in, const int* in_sizes, int n_in,
                              void* d_out, int out_size)
{
    const float* x  = (const float*)d_in[0];  // [64, 4096, 512]
    const float* qm = (const float*)d_in[1];  // [64, 128, 512]
    const float* W  = (const float*)d_in[2];  // [512, 512]
    const float* p  = (const float*)d_in[3];  // [128, 1]
    float* out = (float*)d_out;               // [64, 512]

    // A1: plain launch
    newq_kernel<<<(QSPLIT * BB * (DQE / 4)) / 256, 256>>>(qm, p);

    // A2: PDL-overlapped with A1's tail
    {
        void* args[] = { (void*)&W };
        launch_pdl((const void*)first_kernel,
                   dim3(KSPLIT, BB / BGRP), dim3(512), args);
    }

    // B: PDL-overlapped with A2 (x prefetch runs during A2's drain)
    {
        void* args[] = { (void*)&x, (void*)&out };
        launch_pdl((const void*)attn_partial_kernel,
                   dim3(NSPLIT, BB), dim3(TPB), args);
    }
}

// round 16
// speedup vs baseline: 1.0426x; 1.0203x over previous
#include <cuda_runtime.h>
#include <math.h>

// Problem shape (fixed by the dataset)
#define BB 64
#define SS 4096
#define DXE 512
#define QQ 128
#define DQE 512

#define NSPLIT 16
#define ROWS_PER_SPLIT (SS / NSPLIT)   // 256
#define TPB 256
#define WARPS (TPB / 32)               // 8
#define ROWS_PER_WARP (ROWS_PER_SPLIT / WARPS) // 32

#define KSPLIT 8
#define KCHUNK (DQE / KSPLIT)          // 64

#define QSPLIT 32
#define QC (QQ / QSPLIT)               // 4

#define BGRP 2                         // batches per first_kernel CTA

// Scratch (allocation-free: __device__ globals)
__device__ float g_newq_part[QSPLIT][BB * DQE];
__device__ float g_first_part[KSPLIT][BB * DXE];
__device__ float g_pM[BB * NSPLIT];
__device__ float g_pL[BB * NSPLIT];
__device__ float g_pC[BB * NSPLIT * DXE];
__device__ unsigned int g_cnt[BB];     // zero-init; reset by last CTA each pass

// Streaming float4 load (evict-first): x is read exactly once.
__device__ __forceinline__ float4 ldcs4(const float4* p) {
    return __ldcs(p);
}

// ---------------------------------------------------------------------------
// Kernel A1: new_q partials. 262144 threads (1024 CTAs x 256), 4 float4
// loads/thread. (Measured at its structural floor ~7us.)
// ---------------------------------------------------------------------------
__global__ __launch_bounds__(256) void newq_kernel(
    const float* __restrict__ qm,   // [B, Q, DQ]
    const float* __restrict__ p)    // [Q, 1]
{
    const int idx = blockIdx.x * 256 + threadIdx.x; // 0..262143
    const int c   = idx >> 13;                      // Q-chunk 0..31
    const int rem = idx & 8191;
    const int b   = rem >> 7;                       // batch 0..63
    const int d4  = rem & 127;                      // float4 index 0..127

    const float4* qb = reinterpret_cast<const float4*>(
        qm + (size_t)b * QQ * DQE + (size_t)(c * QC) * DQE) + d4;
    const float* pc = p + c * QC;

    const float4 v0 = __ldcs(qb + 0 * (DQE / 4));
    const float4 v1 = __ldcs(qb + 1 * (DQE / 4));
    const float4 v2 = __ldcs(qb + 2 * (DQE / 4));
    const float4 v3 = __ldcs(qb + 3 * (DQE / 4));
    const float s0 = __ldg(&pc[0]);
    const float s1 = __ldg(&pc[1]);
    const float s2 = __ldg(&pc[2]);
    const float s3 = __ldg(&pc[3]);

    float4 r;
    r.x = fmaf(v0.x, s0, v1.x * s1);
    r.x = fmaf(v2.x, s2, r.x); r.x = fmaf(v3.x, s3, r.x);
    r.y = fmaf(v0.y, s0, v1.y * s1);
    r.y = fmaf(v2.y, s2, r.y); r.y = fmaf(v3.y, s3, r.y);
    r.z = fmaf(v0.z, s0, v1.z * s1);
    r.z = fmaf(v2.z, s2, r.z); r.z = fmaf(v3.z, s3, r.z);
    r.w = fmaf(v0.w, s0, v1.w * s1);
    r.w = fmaf(v2.w, s2, r.w); r.w = fmaf(v3.w, s3, r.w);

    reinterpret_cast<float4*>(&g_newq_part[c][b * DQE])[d4] = r;

    cudaTriggerProgrammaticLaunchCompletion();
}

// ---------------------------------------------------------------------------
// Kernel A2: first_part[kc][b,t] = sum_{d in chunk kc} new_q[b,d]*W[d,t]
// grid = (8, 32) = 256 CTAs x 512 thr. PDL consumer of newq.
// ---------------------------------------------------------------------------
__global__ __launch_bounds__(512) void first_kernel(
    const float* __restrict__ W)    // [DQ, DX]
{
    const int kc = blockIdx.x;      // 0..7
    const int bg = blockIdx.y;      // 0..31
    const int t  = threadIdx.x;     // 0..511

    __shared__ float sq[BGRP][KCHUNK];

    cudaGridDependencySynchronize();

    if (t < BGRP * KCHUNK) {
        const int j = t >> 6;           // batch within group
        const int d = t & 63;
        const int off = (bg * BGRP + j) * DQE + kc * KCHUNK + d;
        float acc[QSPLIT];
#pragma unroll
        for (int c = 0; c < QSPLIT; c++) acc[c] = g_newq_part[c][off];
        float s = 0.f;
#pragma unroll
        for (int c = 0; c < QSPLIT; c++) s += acc[c];
        sq[j][d] = s;
    }
    __syncthreads();

    float acc0 = 0.f, acc1 = 0.f;
    const float* Wc = W + (size_t)(kc * KCHUNK) * DXE + t;
#pragma unroll 16
    for (int d = 0; d < KCHUNK; d++) {
        const float w = Wc[d * DXE];
        acc0 = fmaf(sq[0][d], w, acc0);
        acc1 = fmaf(sq[1][d], w, acc1);
    }
    g_first_part[kc][(bg * BGRP + 0) * DXE + t] = acc0;
    g_first_part[kc][(bg * BGRP + 1) * DXE + t] = acc1;

    cudaTriggerProgrammaticLaunchCompletion();
}

// ---------------------------------------------------------------------------
// Kernel B: fused flash pass + fused last-CTA final reduce. (R15 form,
// but ALL x loads use __ldcs streaming hints — zero register impact.)
// grid = (NSPLIT, B), block = 256.
// ---------------------------------------------------------------------------
__global__ __launch_bounds__(TPB, 4) void attn_partial_kernel(
    const float* __restrict__ x,   // [B, S, DX]
    float* __restrict__ out)       // [B, DX]
{
    const int split = blockIdx.x;
    const int b     = blockIdx.y;
    const int t     = threadIdx.x;
    const int w     = t >> 5;
    const int lane  = t & 31;

    __shared__ float sfirst[DXE];
    __shared__ float sm_m[WARPS];
    __shared__ float sm_l[WARPS];
    __shared__ float4 sm_acc[WARPS][DXE / 4];
    __shared__ int s_last;

    const float4* xb = reinterpret_cast<const float4*>(
        x + (size_t)b * SS * DXE);
    const int s0 = split * ROWS_PER_SPLIT + w;

    // --- prefetch row 0 BEFORE the dependency sync (x doesn't depend on it)
    const float4* xr0 = xb + (size_t)s0 * (DXE / 4);
    float4 pv0 = ldcs4(xr0 + lane);
    float4 pv1 = ldcs4(xr0 + lane + 32);
    float4 pv2 = ldcs4(xr0 + lane + 64);
    float4 pv3 = ldcs4(xr0 + lane + 96);

    // wait for first_kernel's grid (PDL)
    cudaGridDependencySynchronize();

    // sum the 8 split-K partials of `first`
#pragma unroll
    for (int half = 0; half < 2; half++) {
        const int d = t + half * 256;
        float f = 0.f;
#pragma unroll
        for (int kc = 0; kc < KSPLIT; kc++)
            f += g_first_part[kc][b * DXE + d];
        sfirst[d] = f;
    }
    __syncthreads();

    // Per-lane slice of first (as float4, strided by 32 lanes)
    const float4* sf4 = reinterpret_cast<const float4*>(sfirst);
    const float4 f0 = sf4[lane];
    const float4 f1 = sf4[lane + 32];
    const float4 f2 = sf4[lane + 64];
    const float4 f3 = sf4[lane + 96];

    // --- peeled iteration 0 using the prefetched row: m=d, l=1, a=v
    float m, l;
    float4 a0, a1, a2, a3;
    {
        float d;
        d = pv0.x * f0.x;
        d = fmaf(pv0.y, f0.y, d); d = fmaf(pv0.z, f0.z, d); d = fmaf(pv0.w, f0.w, d);
        d = fmaf(pv1.x, f1.x, d); d = fmaf(pv1.y, f1.y, d); d = fmaf(pv1.z, f1.z, d); d = fmaf(pv1.w, f1.w, d);
        d = fmaf(pv2.x, f2.x, d); d = fmaf(pv2.y, f2.y, d); d = fmaf(pv2.z, f2.z, d); d = fmaf(pv2.w, f2.w, d);
        d = fmaf(pv3.x, f3.x, d); d = fmaf(pv3.y, f3.y, d); d = fmaf(pv3.z, f3.z, d); d = fmaf(pv3.w, f3.w, d);
#pragma unroll
        for (int o = 16; o > 0; o >>= 1)
            d += __shfl_xor_sync(0xffffffffu, d, o);
        m = d;
        l = 1.f;
        a0 = pv0; a1 = pv1; a2 = pv2; a3 = pv3;
    }

    for (int r = 1; r < ROWS_PER_WARP; r++) {
        const int s = s0 + WARPS * r;
        const float4* xr = xb + (size_t)s * (DXE / 4);
        // 4 independent streaming LDG.128 per lane -> MLP = 4
        const float4 v0 = ldcs4(xr + lane);
        const float4 v1 = ldcs4(xr + lane + 32);
        const float4 v2 = ldcs4(xr + lane + 64);
        const float4 v3 = ldcs4(xr + lane + 96);

        // dot(first, x_row)
        float d;
        d = v0.x * f0.x;
        d = fmaf(v0.y, f0.y, d); d = fmaf(v0.z, f0.z, d); d = fmaf(v0.w, f0.w, d);
        d = fmaf(v1.x, f1.x, d); d = fmaf(v1.y, f1.y, d); d = fmaf(v1.z, f1.z, d); d = fmaf(v1.w, f1.w, d);
        d = fmaf(v2.x, f2.x, d); d = fmaf(v2.y, f2.y, d); d = fmaf(v2.z, f2.z, d); d = fmaf(v2.w, f2.w, d);
        d = fmaf(v3.x, f3.x, d); d = fmaf(v3.y, f3.y, d); d = fmaf(v3.w, f3.w, d); d = fmaf(v3.z, f3.z, d);
#pragma unroll
        for (int o = 16; o > 0; o >>= 1)
            d += __shfl_xor_sync(0xffffffffu, d, o);

        // online softmax update (d is warp-uniform -> no divergence)
        if (d > m) {
            const float sc = __expf(m - d);
            l *= sc;
            a0.x *= sc; a0.y *= sc; a0.z *= sc; a0.w *= sc;
            a1.x *= sc; a1.y *= sc; a1.z *= sc; a1.w *= sc;
            a2.x *= sc; a2.y *= sc; a2.z *= sc; a2.w *= sc;
            a3.x *= sc; a3.y *= sc; a3.z *= sc; a3.w *= sc;
            m = d;
        }
        const float wgt = __expf(d - m);
        l += wgt;
        a0.x = fmaf(wgt, v0.x, a0.x); a0.y = fmaf(wgt, v0.y, a0.y);
        a0.z = fmaf(wgt, v0.z, a0.z); a0.w = fmaf(wgt, v0.w, a0.w);
        a1.x = fmaf(wgt, v1.x, a1.x); a1.y = fmaf(wgt, v1.y, a1.y);
        a1.z = fmaf(wgt, v1.z, a1.z); a1.w = fmaf(wgt, v1.w, a1.w);
        a2.x = fmaf(wgt, v2.x, a2.x); a2.y = fmaf(wgt, v2.y, a2.y);
        a2.z = fmaf(wgt, v2.z, a2.z); a2.w = fmaf(wgt, v2.w, a2.w);
        a3.x = fmaf(wgt, v3.x, a3.x); a3.y = fmaf(wgt, v3.y, a3.y);
        a3.z = fmaf(wgt, v3.z, a3.z); a3.w = fmaf(wgt, v3.w, a3.w);
    }

    // Stash per-warp partials in shared
    if (lane == 0) { sm_m[w] = m; sm_l[w] = l; }
    sm_acc[w][lane]      = a0;
    sm_acc[w][lane + 32] = a1;
    sm_acc[w][lane + 64] = a2;
    sm_acc[w][lane + 96] = a3;
    __syncthreads();

    // Block combine: 8 warps -> one partial (M, L, ctx[512])
    float M = sm_m[0];
#pragma unroll
    for (int i = 1; i < WARPS; i++) M = fmaxf(M, sm_m[i]);

    float ef[WARPS];
    float L = 0.f;
#pragma unroll
    for (int i = 0; i < WARPS; i++) {
        ef[i] = __expf(sm_m[i] - M);
        L = fmaf(ef[i], sm_l[i], L);
    }

    const float* accf = reinterpret_cast<const float*>(sm_acc); // [WARPS][512]
    const int pidx = b * NSPLIT + split;
    float* pc = g_pC + (size_t)pidx * DXE;
#pragma unroll
    for (int half = 0; half < 2; half++) {
        const int d = t + half * 256;
        float c = 0.f;
#pragma unroll
        for (int i = 0; i < WARPS; i++)
            c = fmaf(ef[i], accf[i * DXE + d], c);
        pc[d] = c;
    }
    if (t == 0) { g_pM[pidx] = M; g_pL[pidx] = L; }

    // ---- fused final reduce: last CTA per batch combines all partials ----
    __syncthreads();
    if (t == 0) {
        __threadfence();
        const unsigned int prev = atomicAdd(&g_cnt[b], 1u);
        s_last = (prev == NSPLIT - 1) ? 1 : 0;
    }
    __syncthreads();
    if (!s_last) return;

    __threadfence();

    __shared__ float rM[NSPLIT];
    __shared__ float rL[NSPLIT];
    if (t < NSPLIT) {
        rM[t] = g_pM[b * NSPLIT + t];
        rL[t] = g_pL[b * NSPLIT + t];
    }

    float cv0[NSPLIT], cv1[NSPLIT];
#pragma unroll
    for (int i = 0; i < NSPLIT; i++) {
        const float* pci = g_pC + (size_t)(b * NSPLIT + i) * DXE;
        cv0[i] = pci[t];
        cv1[i] = pci[t + 256];
    }
    __syncthreads();

    float GM = rM[0];
#pragma unroll
    for (int i = 1; i < NSPLIT; i++) GM = fmaxf(GM, rM[i]);

    float GL = 0.f, c0 = 0.f, c1 = 0.f;
#pragma unroll
    for (int i = 0; i < NSPLIT; i++) {
        const float e = __expf(rM[i] - GM);
        GL = fmaf(e, rL[i], GL);
        c0 = fmaf(e, cv0[i], c0);
        c1 = fmaf(e, cv1[i], c1);
    }
    const float inv = 1.f / GL;
    out[b * DXE + t]       = c0 * inv;
    out[b * DXE + t + 256] = c1 * inv;

    if (t == 0) g_cnt[b] = 0;    // reset for next graph replay
}

// ---------------------------------------------------------------------------
static inline void launch_pdl(const void* func, dim3 grid, dim3 block,
                              void** args)
{
    cudaLaunchConfig_t cfg = {};
    cfg.gridDim = grid;
    cfg.blockDim = block;
    cfg.dynamicSmemBytes = 0;
    cfg.stream = 0;            // default stream (captured by harness)
    cudaLaunchAttribute attr[1];
    attr[0].id = cudaLaunchAttributeProgrammaticStreamSerialization;
    attr[0].val.programmaticStreamSerializationAllowed = 1;
    cfg.attrs = attr;
    cfg.numAttrs = 1;
    cudaLaunchKernelExC(&cfg, func, args);
}

extern "C" void kernel_launch(void* const* d_in, const int* in_sizes, int n_in,
                              void* d_out, int out_size)
{
    const float* x  = (const float*)d_in[0];  // [64, 4096, 512]
    const float* qm = (const float*)d_in[1];  // [64, 128, 512]
    const float* W  = (const float*)d_in[2];  // [512, 512]
    const float* p  = (const float*)d_in[3];  // [128, 1]
    float* out = (float*)d_out;               // [64, 512]

    // A1: plain launch
    newq_kernel<<<(QSPLIT * BB * (DQE / 4)) / 256, 256>>>(qm, p);

    // A2: PDL-overlapped with A1's tail
    {
        void* args[] = { (void*)&W };
        launch_pdl((const void*)first_kernel,
                   dim3(KSPLIT, BB / BGRP), dim3(512), args);
    }

    // B: PDL-overlapped with A2 (x prefetch runs during A2's drain)
    {
        void* args[] = { (void*)&x, (void*)&out };
        launch_pdl((const void*)attn_partial_kernel,
                   dim3(NSPLIT, BB), dim3(TPB), args);
    }
}

// round 17
// speedup vs baseline: 1.0561x; 1.0130x over previous
#include <cuda_runtime.h>
#include <math.h>

// Problem shape (fixed by the dataset)
#define BB 64
#define SS 4096
#define DXE 512
#define QQ 128
#define DQE 512

#define NSPLIT 8
#define ROWS_PER_SPLIT (SS / NSPLIT)   // 512
#define TPB 256
#define WARPS (TPB / 32)               // 8
#define ROWS_PER_WARP (ROWS_PER_SPLIT / WARPS) // 64

#define KSPLIT 8
#define KCHUNK (DQE / KSPLIT)          // 64

#define QSPLIT 32
#define QC (QQ / QSPLIT)               // 4

#define BGRP 2                         // batches per first_kernel CTA

// Scratch (allocation-free: __device__ globals)
__device__ float g_newq_part[QSPLIT][BB * DQE];
__device__ float g_first_part[KSPLIT][BB * DXE];
__device__ float g_pM[BB * NSPLIT];
__device__ float g_pL[BB * NSPLIT];
__device__ float g_pC[BB * NSPLIT * DXE];
__device__ unsigned int g_cnt[BB];     // zero-init; reset by last CTA each pass

// Streaming float4 load (evict-first): x is read exactly once.
__device__ __forceinline__ float4 ldcs4(const float4* p) {
    return __ldcs(p);
}

// ---------------------------------------------------------------------------
// Kernel A1: new_q partials. 262144 threads (1024 CTAs x 256), 4 float4
// loads/thread. (Measured at its structural floor ~7us.)
// ---------------------------------------------------------------------------
__global__ __launch_bounds__(256) void newq_kernel(
    const float* __restrict__ qm,   // [B, Q, DQ]
    const float* __restrict__ p)    // [Q, 1]
{
    const int idx = blockIdx.x * 256 + threadIdx.x; // 0..262143
    const int c   = idx >> 13;                      // Q-chunk 0..31
    const int rem = idx & 8191;
    const int b   = rem >> 7;                       // batch 0..63
    const int d4  = rem & 127;                      // float4 index 0..127

    const float4* qb = reinterpret_cast<const float4*>(
        qm + (size_t)b * QQ * DQE + (size_t)(c * QC) * DQE) + d4;
    const float* pc = p + c * QC;

    const float4 v0 = __ldcs(qb + 0 * (DQE / 4));
    const float4 v1 = __ldcs(qb + 1 * (DQE / 4));
    const float4 v2 = __ldcs(qb + 2 * (DQE / 4));
    const float4 v3 = __ldcs(qb + 3 * (DQE / 4));
    const float s0 = __ldg(&pc[0]);
    const float s1 = __ldg(&pc[1]);
    const float s2 = __ldg(&pc[2]);
    const float s3 = __ldg(&pc[3]);

    float4 r;
    r.x = fmaf(v0.x, s0, v1.x * s1);
    r.x = fmaf(v2.x, s2, r.x); r.x = fmaf(v3.x, s3, r.x);
    r.y = fmaf(v0.y, s0, v1.y * s1);
    r.y = fmaf(v2.y, s2, r.y); r.y = fmaf(v3.y, s3, r.y);
    r.z = fmaf(v0.z, s0, v1.z * s1);
    r.z = fmaf(v2.z, s2, r.z); r.z = fmaf(v3.z, s3, r.z);
    r.w = fmaf(v0.w, s0, v1.w * s1);
    r.w = fmaf(v2.w, s2, r.w); r.w = fmaf(v3.w, s3, r.w);

    reinterpret_cast<float4*>(&g_newq_part[c][b * DQE])[d4] = r;

    cudaTriggerProgrammaticLaunchCompletion();
}

// ---------------------------------------------------------------------------
// Kernel A2: first_part[kc][b,t] = sum_{d in chunk kc} new_q[b,d]*W[d,t]
// grid = (8, 32) = 256 CTAs x 512 thr. PDL consumer of newq.
// ---------------------------------------------------------------------------
__global__ __launch_bounds__(512) void first_kernel(
    const float* __restrict__ W)    // [DQ, DX]
{
    const int kc = blockIdx.x;      // 0..7
    const int bg = blockIdx.y;      // 0..31
    const int t  = threadIdx.x;     // 0..511

    __shared__ float sq[BGRP][KCHUNK];

    cudaGridDependencySynchronize();

    if (t < BGRP * KCHUNK) {
        const int j = t >> 6;           // batch within group
        const int d = t & 63;
        const int off = (bg * BGRP + j) * DQE + kc * KCHUNK + d;
        float acc[QSPLIT];
#pragma unroll
        for (int c = 0; c < QSPLIT; c++) acc[c] = g_newq_part[c][off];
        float s = 0.f;
#pragma unroll
        for (int c = 0; c < QSPLIT; c++) s += acc[c];
        sq[j][d] = s;
    }
    __syncthreads();

    float acc0 = 0.f, acc1 = 0.f;
    const float* Wc = W + (size_t)(kc * KCHUNK) * DXE + t;
#pragma unroll 16
    for (int d = 0; d < KCHUNK; d++) {
        const float w = Wc[d * DXE];
        acc0 = fmaf(sq[0][d], w, acc0);
        acc1 = fmaf(sq[1][d], w, acc1);
    }
    g_first_part[kc][(bg * BGRP + 0) * DXE + t] = acc0;
    g_first_part[kc][(bg * BGRP + 1) * DXE + t] = acc1;

    cudaTriggerProgrammaticLaunchCompletion();
}

// ---------------------------------------------------------------------------
// Kernel B: fused flash pass + fused last-CTA final reduce.
// NSPLIT=8 -> grid (8, 64) = 512 CTAs: the WHOLE grid fits in one wave at
// 4 CTAs/SM (592 slots), eliminating wave quantization.
// ---------------------------------------------------------------------------
__global__ __launch_bounds__(TPB, 4) void attn_partial_kernel(
    const float* __restrict__ x,   // [B, S, DX]
    float* __restrict__ out)       // [B, DX]
{
    const int split = blockIdx.x;
    const int b     = blockIdx.y;
    const int t     = threadIdx.x;
    const int w     = t >> 5;
    const int lane  = t & 31;

    __shared__ float sfirst[DXE];
    __shared__ float sm_m[WARPS];
    __shared__ float sm_l[WARPS];
    __shared__ float4 sm_acc[WARPS][DXE / 4];
    __shared__ int s_last;

    const float4* xb = reinterpret_cast<const float4*>(
        x + (size_t)b * SS * DXE);
    const int s0 = split * ROWS_PER_SPLIT + w;

    // --- prefetch row 0 BEFORE the dependency sync (x doesn't depend on it)
    const float4* xr0 = xb + (size_t)s0 * (DXE / 4);
    float4 pv0 = ldcs4(xr0 + lane);
    float4 pv1 = ldcs4(xr0 + lane + 32);
    float4 pv2 = ldcs4(xr0 + lane + 64);
    float4 pv3 = ldcs4(xr0 + lane + 96);

    // wait for first_kernel's grid (PDL)
    cudaGridDependencySynchronize();

    // sum the 8 split-K partials of `first`
#pragma unroll
    for (int half = 0; half < 2; half++) {
        const int d = t + half * 256;
        float f = 0.f;
#pragma unroll
        for (int kc = 0; kc < KSPLIT; kc++)
            f += g_first_part[kc][b * DXE + d];
        sfirst[d] = f;
    }
    __syncthreads();

    // Per-lane slice of first (as float4, strided by 32 lanes)
    const float4* sf4 = reinterpret_cast<const float4*>(sfirst);
    const float4 f0 = sf4[lane];
    const float4 f1 = sf4[lane + 32];
    const float4 f2 = sf4[lane + 64];
    const float4 f3 = sf4[lane + 96];

    // --- peeled iteration 0 using the prefetched row: m=d, l=1, a=v
    float m, l;
    float4 a0, a1, a2, a3;
    {
        float d;
        d = pv0.x * f0.x;
        d = fmaf(pv0.y, f0.y, d); d = fmaf(pv0.z, f0.z, d); d = fmaf(pv0.w, f0.w, d);
        d = fmaf(pv1.x, f1.x, d); d = fmaf(pv1.y, f1.y, d); d = fmaf(pv1.z, f1.z, d); d = fmaf(pv1.w, f1.w, d);
        d = fmaf(pv2.x, f2.x, d); d = fmaf(pv2.y, f2.y, d); d = fmaf(pv2.z, f2.z, d); d = fmaf(pv2.w, f2.w, d);
        d = fmaf(pv3.x, f3.x, d); d = fmaf(pv3.y, f3.y, d); d = fmaf(pv3.z, f3.z, d); d = fmaf(pv3.w, f3.w, d);
#pragma unroll
        for (int o = 16; o > 0; o >>= 1)
            d += __shfl_xor_sync(0xffffffffu, d, o);
        m = d;
        l = 1.f;
        a0 = pv0; a1 = pv1; a2 = pv2; a3 = pv3;
    }

    for (int r = 1; r < ROWS_PER_WARP; r++) {
        const int s = s0 + WARPS * r;
        const float4* xr = xb + (size_t)s * (DXE / 4);
        // 4 independent streaming LDG.128 per lane -> MLP = 4
        const float4 v0 = ldcs4(xr + lane);
        const float4 v1 = ldcs4(xr + lane + 32);
        const float4 v2 = ldcs4(xr + lane + 64);
        const float4 v3 = ldcs4(xr + lane + 96);

        // dot(first, x_row)
        float d;
        d = v0.x * f0.x;
        d = fmaf(v0.y, f0.y, d); d = fmaf(v0.z, f0.z, d); d = fmaf(v0.w, f0.w, d);
        d = fmaf(v1.x, f1.x, d); d = fmaf(v1.y, f1.y, d); d = fmaf(v1.z, f1.z, d); d = fmaf(v1.w, f1.w, d);
        d = fmaf(v2.x, f2.x, d); d = fmaf(v2.y, f2.y, d); d = fmaf(v2.z, f2.z, d); d = fmaf(v2.w, f2.w, d);
        d = fmaf(v3.x, f3.x, d); d = fmaf(v3.y, f3.y, d); d = fmaf(v3.z, f3.z, d); d = fmaf(v3.w, f3.w, d);
#pragma unroll
        for (int o = 16; o > 0; o >>= 1)
            d += __shfl_xor_sync(0xffffffffu, d, o);

        // online softmax update (d is warp-uniform -> no divergence)
        if (d > m) {
            const float sc = __expf(m - d);
            l *= sc;
            a0.x *= sc; a0.y *= sc; a0.z *= sc; a0.w *= sc;
            a1.x *= sc; a1.y *= sc; a1.z *= sc; a1.w *= sc;
            a2.x *= sc; a2.y *= sc; a2.z *= sc; a2.w *= sc;
            a3.x *= sc; a3.y *= sc; a3.z *= sc; a3.w *= sc;
            m = d;
        }
        const float wgt = __expf(d - m);
        l += wgt;
        a0.x = fmaf(wgt, v0.x, a0.x); a0.y = fmaf(wgt, v0.y, a0.y);
        a0.z = fmaf(wgt, v0.z, a0.z); a0.w = fmaf(wgt, v0.w, a0.w);
        a1.x = fmaf(wgt, v1.x, a1.x); a1.y = fmaf(wgt, v1.y, a1.y);
        a1.z = fmaf(wgt, v1.z, a1.z); a1.w = fmaf(wgt, v1.w, a1.w);
        a2.x = fmaf(wgt, v2.x, a2.x); a2.y = fmaf(wgt, v2.y, a2.y);
        a2.z = fmaf(wgt, v2.z, a2.z); a2.w = fmaf(wgt, v2.w, a2.w);
        a3.x = fmaf(wgt, v3.x, a3.x); a3.y = fmaf(wgt, v3.y, a3.y);
        a3.z = fmaf(wgt, v3.z, a3.z); a3.w = fmaf(wgt, v3.w, a3.w);
    }

    // Stash per-warp partials in shared
    if (lane == 0) { sm_m[w] = m; sm_l[w] = l; }
    sm_acc[w][lane]      = a0;
    sm_acc[w][lane + 32] = a1;
    sm_acc[w][lane + 64] = a2;
    sm_acc[w][lane + 96] = a3;
    __syncthreads();

    // Block combine: 8 warps -> one partial (M, L, ctx[512])
    float M = sm_m[0];
#pragma unroll
    for (int i = 1; i < WARPS; i++) M = fmaxf(M, sm_m[i]);

    float ef[WARPS];
    float L = 0.f;
#pragma unroll
    for (int i = 0; i < WARPS; i++) {
        ef[i] = __expf(sm_m[i] - M);
        L = fmaf(ef[i], sm_l[i], L);
    }

    const float* accf = reinterpret_cast<const float*>(sm_acc); // [WARPS][512]
    const int pidx = b * NSPLIT + split;
    float* pc = g_pC + (size_t)pidx * DXE;
#pragma unroll
    for (int half = 0; half < 2; half++) {
        const int d = t + half * 256;
        float c = 0.f;
#pragma unroll
        for (int i = 0; i < WARPS; i++)
            c = fmaf(ef[i], accf[i * DXE + d], c);
        pc[d] = c;
    }
    if (t == 0) { g_pM[pidx] = M; g_pL[pidx] = L; }

    // ---- fused final reduce: last CTA per batch combines all partials ----
    __syncthreads();
    if (t == 0) {
        __threadfence();
        const unsigned int prev = atomicAdd(&g_cnt[b], 1u);
        s_last = (prev == NSPLIT - 1) ? 1 : 0;
    }
    __syncthreads();
    if (!s_last) return;

    __threadfence();

    __shared__ float rM[NSPLIT];
    __shared__ float rL[NSPLIT];
    if (t < NSPLIT) {
        rM[t] = g_pM[b * NSPLIT + t];
        rL[t] = g_pL[b * NSPLIT + t];
    }

    float cv0[NSPLIT], cv1[NSPLIT];
#pragma unroll
    for (int i = 0; i < NSPLIT; i++) {
        const float* pci = g_pC + (size_t)(b * NSPLIT + i) * DXE;
        cv0[i] = pci[t];
        cv1[i] = pci[t + 256];
    }
    __syncthreads();

    float GM = rM[0];
#pragma unroll
    for (int i = 1; i < NSPLIT; i++) GM = fmaxf(GM, rM[i]);

    float GL = 0.f, c0 = 0.f, c1 = 0.f;
#pragma unroll
    for (int i = 0; i < NSPLIT; i++) {
        const float e = __expf(rM[i] - GM);
        GL = fmaf(e, rL[i], GL);
        c0 = fmaf(e, cv0[i], c0);
        c1 = fmaf(e, cv1[i], c1);
    }
    const float inv = 1.f / GL;
    out[b * DXE + t]       = c0 * inv;
    out[b * DXE + t + 256] = c1 * inv;

    if (t == 0) g_cnt[b] = 0;    // reset for next graph replay
}

// ---------------------------------------------------------------------------
static inline void launch_pdl(const void* func, dim3 grid, dim3 block,
                              void** args)
{
    cudaLaunchConfig_t cfg = {};
    cfg.gridDim = grid;
    cfg.blockDim = block;
    cfg.dynamicSmemBytes = 0;
    cfg.stream = 0;            // default stream (captured by harness)
    cudaLaunchAttribute attr[1];
    attr[0].id = cudaLaunchAttributeProgrammaticStreamSerialization;
    attr[0].val.programmaticStreamSerializationAllowed = 1;
    cfg.attrs = attr;
    cfg.numAttrs = 1;
    cudaLaunchKernelExC(&cfg, func, args);
}

extern "C" void kernel_launch(void* const* d_in, const int* in_sizes, int n_in,
                              void* d_out, int out_size)
{
    const float* x  = (const float*)d_in[0];  // [64, 4096, 512]
    const float* qm = (const float*)d_in[1];  // [64, 128, 512]
    const float* W  = (const float*)d_in[2];  // [512, 512]
    const float* p  = (const float*)d_in[3];  // [128, 1]
    float* out = (float*)d_out;               // [64, 512]

    // A1: plain launch
    newq_kernel<<<(QSPLIT * BB * (DQE / 4)) / 256, 256>>>(qm, p);

    // A2: PDL-overlapped with A1's tail
    {
        void* args[] = { (void*)&W };
        launch_pdl((const void*)first_kernel,
                   dim3(KSPLIT, BB / BGRP), dim3(512), args);
    }

    // B: PDL-overlapped with A2 (x prefetch runs during A2's drain)
    {
        void* args[] = { (void*)&x, (void*)&out };
        launch_pdl((const void*)attn_partial_kernel,
                   dim3(NSPLIT, BB), dim3(TPB), args);
    }
}